// round 11
// baseline (speedup 1.0000x reference)
#include <cuda_runtime.h>
#include <cuda_bf16.h>
#include <math.h>

// EdgeEmbeddingBlock: out_r[b,k,i,j] = radial[b,i] * na[b,k] * ylm_r[b,j]
//                     out_i[b,k,i,j] = radial[b,i] * na[b,k] * ylm_i[b,j]
// E=60000, K=10, NMAX=8, J=16. Output [combined_r | combined_i], 614 MB written.
//
// R10 best (86.2us): register-resident, 1 warp/edge, __stcs, 32-bit indexing.
// R11: Blackwell 256-bit stores (st.global.cs.v8.f32) — 10 store insts/edge
// instead of 20, testing LSU-issue / DRAM co-saturation.
// Lane mapping for float8 f = lane + 32*it:
//   j8 group = lane&1, i = (lane>>1)&7, k = (lane>>4) + 2*it  (it = 0..4)

#define KATTR 10
#define F8_PER_EDGE 160u         // 1280 floats / 8

#define SEL2(g,a,b) ((g) ? (b) : (a))

#define STG256_CS(ptr, v) \
    asm volatile("st.global.cs.v8.f32 [%0], {%1,%2,%3,%4,%5,%6,%7,%8};" \
        :: "l"(ptr), "f"((v)[0]), "f"((v)[1]), "f"((v)[2]), "f"((v)[3]), \
           "f"((v)[4]), "f"((v)[5]), "f"((v)[6]), "f"((v)[7]) : "memory")

__global__ __launch_bounds__(256, 6)
void edge_embed_kernel(const int* __restrict__ edge_index,
                       const float* __restrict__ lens,
                       const float* __restrict__ vecs,
                       const float* __restrict__ attrs,
                       float* __restrict__ out,
                       int E)
{
    const int warp = threadIdx.x >> 5;
    const int lane = threadIdx.x & 31;
    const int e = blockIdx.x * 8 + warp;
    if (e >= E) return;

    // ---- per-edge scalars (broadcast loads) ----
    const float x  = lens[e];
    const float vx = vecs[3 * e + 0];
    const float vy = vecs[3 * e + 1];
    const float vz = vecs[3 * e + 2];
    const int sender = edge_index[e];   // edge_index[0, e]

    // lanes 0..9: node attrs for shuffle distribution
    float na_v = 0.0f;
    if (lane < KATTR) na_v = attrs[sender * KATTR + lane];

    // ---- radial: this lane needs rad[i], i = (lane>>1)&7 ----
    const float u  = x * 0.2f;
    const float u2 = u * u, u3 = u2 * u;
    const float u6 = u3 * u3, u7 = u6 * u, u8 = u7 * u;
    float env = 1.0f - 28.0f * u6 + 48.0f * u7 - 21.0f * u8;
    env = (u < 1.0f) ? env : 0.0f;
    const float base = 0.63245553203f * env / x;          // sqrt(2/5) * env / x
    const float w = (float)(((lane >> 1) & 7) + 1) * 0.62831853071f;  // n*pi/R_CUT
    const float r_l = base * sinf(w * x);

    // ---- zonal harmonics (all lanes, straight-line) ----
    const float nrm = sqrtf(vx * vx + vy * vy + vz * vz);
    const float inv = 1.0f / fmaxf(nrm, 1e-9f);
    const float ux = vx * inv, uy = vy * inv, uz = vz * inv;
    const float ct  = uz;
    const float st2 = fmaxf(1.0f - ct * ct, 0.0f);
    const float st  = sqrtf(st2);
    const float rxy = sqrtf(ux * ux + uy * uy);
    float c1, s1;
    if (rxy > 0.0f) { const float ir = 1.0f / rxy; c1 = ux * ir; s1 = uy * ir; }
    else            { c1 = 1.0f; s1 = 0.0f; }
    const float c2 = 2.0f * c1 * c1 - 1.0f;
    const float s2 = 2.0f * s1 * c1;
    const float c3 = c1 * c2 - s1 * s2;
    const float s3 = s1 * c2 + c1 * s2;

    const float P11 = -st;
    const float P22 = 3.0f * st2;
    const float P33 = -15.0f * st2 * st;
    const float P21 = -3.0f * ct * st;
    const float P32 = 15.0f * ct * st2;
    const float P20 = 1.5f * ct * ct - 0.5f;
    const float P31 = 0.5f * (5.0f * ct * P21 + 3.0f * st);
    const float P30 = ct * (2.5f * ct * ct - 1.5f);

    const float n00 = 0.28209479177f;
    const float n10 = 0.48860251190f, n11 = 0.34549414947f;
    const float n20 = 0.63078313051f, n21 = 0.25751613469f, n22 = 0.12875806734f;
    const float n30 = 0.74635266518f, n31 = 0.21545345607f, n32 = 0.06813236028f,
                n33 = 0.02781492157f;

    const float a  = n11 * P11;
    const float b1 = n21 * P21, b2 = n22 * P22;
    const float d1 = n31 * P31, d2 = n32 * P32, d3 = n33 * P33;

    // ylm 8-wide group: g=0 -> j 0..7, g=1 -> j 8..15
    const int g = lane & 1;
    float yr8[8], yi8[8];
    yr8[0] = SEL2(g, n00,       b2 * c2);
    yr8[1] = SEL2(g, -a * c1,  -d3 * c3);
    yr8[2] = SEL2(g, n10 * ct,  d2 * c2);
    yr8[3] = SEL2(g, a * c1,   -d1 * c1);
    yr8[4] = SEL2(g, b2 * c2,   n30 * P30);
    yr8[5] = SEL2(g, -b1 * c1,  d1 * c1);
    yr8[6] = SEL2(g, n20 * P20, d2 * c2);
    yr8[7] = SEL2(g, b1 * c1,   d3 * c3);
    yi8[0] = SEL2(g, 0.0f,      b2 * s2);
    yi8[1] = SEL2(g, a * s1,    d3 * s3);
    yi8[2] = SEL2(g, 0.0f,     -d2 * s2);
    yi8[3] = SEL2(g, a * s1,    d1 * s1);
    yi8[4] = SEL2(g, -b2 * s2,  0.0f);
    yi8[5] = SEL2(g, b1 * s1,   d1 * s1);
    yi8[6] = SEL2(g, 0.0f,      d2 * s2);
    yi8[7] = SEL2(g, b1 * s1,   d3 * s3);

    // ---- 160 float8 per half: 5 x STG.256 per region per lane ----
    const int khalf = lane >> 4;   // 0 or 1
    float* __restrict__ pr = out + ((unsigned)e * F8_PER_EDGE + (unsigned)lane) * 8u;
    float* __restrict__ pi = out + (((unsigned)E + (unsigned)e) * F8_PER_EDGE + (unsigned)lane) * 8u;

    #pragma unroll
    for (int it = 0; it < 5; ++it) {
        const int k = khalf + 2 * it;
        const float s = r_l * __shfl_sync(0xffffffffu, na_v, k);
        float vr[8], vi[8];
        #pragma unroll
        for (int q = 0; q < 8; ++q) { vr[q] = s * yr8[q]; vi[q] = s * yi8[q]; }
        STG256_CS(pr + 256 * it, vr);
        STG256_CS(pi + 256 * it, vi);
    }
}

extern "C" void kernel_launch(void* const* d_in, const int* in_sizes, int n_in,
                              void* d_out, int out_size)
{
    const int*   edge_index = (const int*)d_in[0];    // (2, E) int32
    const float* lens       = (const float*)d_in[1];  // (E, 1) f32
    const float* vecs       = (const float*)d_in[2];  // (E, 3) f32
    const float* attrs      = (const float*)d_in[3];  // (N_NODES, 10) f32
    float* out = (float*)d_out;

    const int E = in_sizes[1];   // edge_lenghts element count
    const int blocks = (E + 7) / 8;
    edge_embed_kernel<<<blocks, 256>>>(edge_index, lens, vecs, attrs, out, E);
}

// round 12
// speedup vs baseline: 1.0313x; 1.0313x over previous
#include <cuda_runtime.h>
#include <cuda_bf16.h>
#include <math.h>

// EdgeEmbeddingBlock: out_r[b,k,i,j] = radial[b,i] * na[b,k] * ylm_r[b,j]
//                     out_i[b,k,i,j] = radial[b,i] * na[b,k] * ylm_i[b,j]
// E=60000, K=10, NMAX=8, J=16. Output [combined_r | combined_i], 614 MB written.
//
// FINAL converged config (R10, 86.24us = HBM write-path floor, ~6.4 TB/s wire):
// register-resident expansion, 1 warp/edge, __stcs STG.128 streams, 256-thread
// blocks, 32-bit output indexing, split r/i store passes. All other levers
// (occupancy, persistence, block size, stwt/write-back, STG.256) measured worse.

#define KATTR 10
#define F4_PER_EDGE 320u         // 1280 floats / 4

#define SEL4(g,a,b,c,d) ((g)==0?(a):((g)==1?(b):((g)==2?(c):(d))))

__global__ __launch_bounds__(256, 6)
void edge_embed_kernel(const int* __restrict__ edge_index,
                       const float* __restrict__ lens,
                       const float* __restrict__ vecs,
                       const float* __restrict__ attrs,
                       float* __restrict__ out,
                       int E)
{
    const int warp = threadIdx.x >> 5;
    const int lane = threadIdx.x & 31;
    const int e = blockIdx.x * 8 + warp;
    if (e >= E) return;

    // ---- per-edge scalars (broadcast loads) ----
    const float x  = lens[e];
    const float vx = vecs[3 * e + 0];
    const float vy = vecs[3 * e + 1];
    const float vz = vecs[3 * e + 2];
    const int sender = edge_index[e];   // edge_index[0, e]

    // lanes 0..9: node attrs for shuffle distribution
    float na_v = 0.0f;
    if (lane < KATTR) na_v = attrs[sender * KATTR + lane];

    // ---- radial: each lane computes rad[lane>>2] (poly cutoff p=6, R_CUT=5) ----
    const float u  = x * 0.2f;
    const float u2 = u * u, u3 = u2 * u;
    const float u6 = u3 * u3, u7 = u6 * u, u8 = u7 * u;
    float env = 1.0f - 28.0f * u6 + 48.0f * u7 - 21.0f * u8;
    env = (u < 1.0f) ? env : 0.0f;
    const float base = 0.63245553203f * env / x;          // sqrt(2/5) * env / x
    const float w = (float)((lane >> 2) + 1) * 0.62831853071f;  // n*pi/R_CUT
    const float r_l = base * sinf(w * x);

    // ---- zonal harmonics (all lanes, straight-line) ----
    const float nrm = sqrtf(vx * vx + vy * vy + vz * vz);
    const float inv = 1.0f / fmaxf(nrm, 1e-9f);
    const float ux = vx * inv, uy = vy * inv, uz = vz * inv;
    const float ct  = uz;
    const float st2 = fmaxf(1.0f - ct * ct, 0.0f);
    const float st  = sqrtf(st2);
    const float rxy = sqrtf(ux * ux + uy * uy);
    float c1, s1;
    if (rxy > 0.0f) { const float ir = 1.0f / rxy; c1 = ux * ir; s1 = uy * ir; }
    else            { c1 = 1.0f; s1 = 0.0f; }
    const float c2 = 2.0f * c1 * c1 - 1.0f;
    const float s2 = 2.0f * s1 * c1;
    const float c3 = c1 * c2 - s1 * s2;
    const float s3 = s1 * c2 + c1 * s2;

    const float P11 = -st;
    const float P22 = 3.0f * st2;
    const float P33 = -15.0f * st2 * st;
    const float P21 = -3.0f * ct * st;
    const float P32 = 15.0f * ct * st2;
    const float P20 = 1.5f * ct * ct - 0.5f;
    const float P31 = 0.5f * (5.0f * ct * P21 + 3.0f * st);
    const float P30 = ct * (2.5f * ct * ct - 1.5f);

    const float n00 = 0.28209479177f;
    const float n10 = 0.48860251190f, n11 = 0.34549414947f;
    const float n20 = 0.63078313051f, n21 = 0.25751613469f, n22 = 0.12875806734f;
    const float n30 = 0.74635266518f, n31 = 0.21545345607f, n32 = 0.06813236028f,
                n33 = 0.02781492157f;

    const float a  = n11 * P11;
    const float b1 = n21 * P21, b2 = n22 * P22;
    const float d1 = n31 * P31, d2 = n32 * P32, d3 = n33 * P33;

    // ylm groups (j = 4g .. 4g+3), select this lane's group g = lane & 3
    const int g = lane & 3;
    float4 yr4, yi4;
    yr4.x = SEL4(g, n00,       b2 * c2,   b2 * c2,  n30 * P30);
    yr4.y = SEL4(g, -a * c1,  -b1 * c1,  -d3 * c3,  d1 * c1);
    yr4.z = SEL4(g, n10 * ct,  n20 * P20, d2 * c2,  d2 * c2);
    yr4.w = SEL4(g, a * c1,    b1 * c1,  -d1 * c1,  d3 * c3);
    yi4.x = SEL4(g, 0.0f,     -b2 * s2,   b2 * s2,  0.0f);
    yi4.y = SEL4(g, a * s1,    b1 * s1,   d3 * s3,  d1 * s1);
    yi4.z = SEL4(g, 0.0f,      0.0f,     -d2 * s2,  d2 * s2);
    yi4.w = SEL4(g, a * s1,    b1 * s1,   d1 * s1,  d3 * s3);

    // ---- per-k scales (shuffled once, reused by both passes) ----
    float sk[KATTR];
    #pragma unroll
    for (int it = 0; it < KATTR; ++it)
        sk[it] = r_l * __shfl_sync(0xffffffffu, na_v, it);

    // ---- 32-bit indexed, immediate-offset streaming stores ----
    float4* __restrict__ out4 = (float4*)out;
    float4* __restrict__ pr = out4 + ((unsigned)e * F4_PER_EDGE + (unsigned)lane);
    float4* __restrict__ pi = out4 + (((unsigned)E + (unsigned)e) * F4_PER_EDGE + (unsigned)lane);

    #pragma unroll
    for (int it = 0; it < KATTR; ++it) {
        const float s = sk[it];
        float4 orr = make_float4(s * yr4.x, s * yr4.y, s * yr4.z, s * yr4.w);
        __stcs(pr + 32 * it, orr);
    }
    #pragma unroll
    for (int it = 0; it < KATTR; ++it) {
        const float s = sk[it];
        float4 oii = make_float4(s * yi4.x, s * yi4.y, s * yi4.z, s * yi4.w);
        __stcs(pi + 32 * it, oii);
    }
}

extern "C" void kernel_launch(void* const* d_in, const int* in_sizes, int n_in,
                              void* d_out, int out_size)
{
    const int*   edge_index = (const int*)d_in[0];    // (2, E) int32
    const float* lens       = (const float*)d_in[1];  // (E, 1) f32
    const float* vecs       = (const float*)d_in[2];  // (E, 3) f32
    const float* attrs      = (const float*)d_in[3];  // (N_NODES, 10) f32
    float* out = (float*)d_out;

    const int E = in_sizes[1];   // edge_lenghts element count
    const int blocks = (E + 7) / 8;
    edge_embed_kernel<<<blocks, 256>>>(edge_index, lens, vecs, attrs, out, E);
}